// round 8
// baseline (speedup 1.0000x reference)
#include <cuda_runtime.h>
#include <cuda_bf16.h>
#include <math.h>

// NNUE HalfKA inference, two-phase:
//  Phase 1: g_comb[f] = bf16(W_ft[f] + W_fft[f % 768])   (96 MB, mostly L2-resident)
//  Phase 2: per batch element, gather 2x32 bf16 rows from g_comb,
//           fp32 (packed f32x2) accumulate, add biases, clip, output dot, sigmoid.
//  Gather processes STM then NSTM sequentially so only 8 accumulator regs are
//  live in the hot loop -> ~36 regs -> high occupancy for latency hiding.
//
// Shapes: B=8192, FPP=32, FT_OUT=1024, N_FEAT=49152, N_VFEAT=768.

#define FT_OUT   1024
#define FPP      32
#define NVFEAT   768
#define NFEAT    49152
#define BLD_THREADS 256
#define GTH_THREADS 128   // 128 threads * 8 dims (16 B bf16) = one 2048 B row

// 96 MB combined bf16 table (static device scratch — no runtime allocation)
__device__ __nv_bfloat16 g_comb[(size_t)NFEAT * FT_OUT];

// ---- packed f32x2 helpers (sm_103a FFMA2 path; ptxas won't emit from C++) ----
__device__ __forceinline__ unsigned long long pack_f2(float a, float b) {
    unsigned long long r;
    asm("mov.b64 %0, {%1, %2};" : "=l"(r) : "f"(a), "f"(b));
    return r;
}
__device__ __forceinline__ void unpack_f2(unsigned long long r, float& a, float& b) {
    asm("mov.b64 {%0, %1}, %2;" : "=f"(a), "=f"(b) : "l"(r));
}
__device__ __forceinline__ unsigned long long fma_f2(unsigned long long a,
                                                     unsigned long long b,
                                                     unsigned long long c) {
    unsigned long long d;
    asm("fma.rn.f32x2 %0, %1, %2, %3;" : "=l"(d) : "l"(a), "l"(b), "l"(c));
    return d;
}
// bf16x2 (one u32) -> packed f32x2 (lo = bits<<16, hi = bits&0xffff0000)
__device__ __forceinline__ unsigned long long bf2_to_f2(unsigned int p) {
    unsigned long long r;
    asm("{\n\t"
        ".reg .b32 lo, hi;\n\t"
        "shl.b32 lo, %1, 16;\n\t"
        "and.b32 hi, %1, 0xffff0000;\n\t"
        "mov.b64 %0, {lo, hi};\n\t"
        "}" : "=l"(r) : "r"(p));
    return r;
}

// ---------------- Phase 1: build combined bf16 table ----------------
__global__ __launch_bounds__(BLD_THREADS)
void build_comb_kernel(const float* __restrict__ W_ft,
                       const float* __restrict__ W_fft)
{
    const int f = blockIdx.x;            // 0..NFEAT-1
    const int c = threadIdx.x * 4;       // 0..1020
    const size_t base = (size_t)f * FT_OUT + c;
    // W_ft is streamed exactly once: evict-first so it doesn't thrash the
    // freshly written comb table out of L2.
    const float4 a = __ldcs((const float4*)(W_ft + base));
    const float4 v = __ldg((const float4*)(W_fft + (size_t)(f % NVFEAT) * FT_OUT + c));

    __nv_bfloat162 lo = __floats2bfloat162_rn(a.x + v.x, a.y + v.y);
    __nv_bfloat162 hi = __floats2bfloat162_rn(a.z + v.z, a.w + v.w);
    uint2 pack;
    pack.x = *(unsigned int*)&lo;
    pack.y = *(unsigned int*)&hi;
    *(uint2*)(g_comb + base) = pack;
}

// one side: gather FPP rows, fp32x2-accumulate, clip, partial output dot
__device__ __forceinline__ float side_accum(
    const char* __restrict__ base,
    const int* __restrict__ s_off,
    const unsigned long long* __restrict__ s_valp,
    const float* __restrict__ b_ft,
    const float* __restrict__ b_fft,
    const float* __restrict__ W_out_side,
    int d)
{
    unsigned long long acc[4];
    {
        float4 bf0 = *(const float4*)(b_ft  + d);
        float4 bf1 = *(const float4*)(b_ft  + d + 4);
        float4 bb0 = *(const float4*)(b_fft + d);
        float4 bb1 = *(const float4*)(b_fft + d + 4);
        acc[0] = pack_f2(bf0.x + bb0.x, bf0.y + bb0.y);
        acc[1] = pack_f2(bf0.z + bb0.z, bf0.w + bb0.w);
        acc[2] = pack_f2(bf1.x + bb1.x, bf1.y + bb1.y);
        acc[3] = pack_f2(bf1.z + bb1.z, bf1.w + bb1.w);
    }

    #pragma unroll 4
    for (int i = 0; i < FPP; i++) {
        const unsigned long long vv = s_valp[i];
        const uint4 p = *(const uint4*)(base + s_off[i]);   // 8 bf16 weights
        acc[0] = fma_f2(bf2_to_f2(p.x), vv, acc[0]);
        acc[1] = fma_f2(bf2_to_f2(p.y), vv, acc[1]);
        acc[2] = fma_f2(bf2_to_f2(p.z), vv, acc[2]);
        acc[3] = fma_f2(bf2_to_f2(p.w), vv, acc[3]);
    }

    // clip + partial dot with W_out slice -> collapses acc into one scalar
    float4 w0 = *(const float4*)(W_out_side + d);
    float4 w1 = *(const float4*)(W_out_side + d + 4);
    float h[8];
    unpack_f2(acc[0], h[0], h[1]);
    unpack_f2(acc[1], h[2], h[3]);
    unpack_f2(acc[2], h[4], h[5]);
    unpack_f2(acc[3], h[6], h[7]);
    float wv[8] = {w0.x, w0.y, w0.z, w0.w, w1.x, w1.y, w1.z, w1.w};
    float p = 0.f;
    #pragma unroll
    for (int k = 0; k < 8; k++)
        p = fmaf(fminf(fmaxf(h[k], 0.f), 1.f), wv[k], p);
    return p;
}

// ---------------- Phase 2: gather + epilogue ----------------
__global__ __launch_bounds__(GTH_THREADS, 14)
void nnue_gather_kernel(
    const float* __restrict__ values,     // [NNZ]
    const int*   __restrict__ stm_feat,   // [NNZ]
    const int*   __restrict__ nstm_feat,  // [NNZ]
    const float* __restrict__ b_ft,       // [1024]
    const float* __restrict__ b_fft,      // [1024]
    const float* __restrict__ W_out,      // [2048]
    const float* __restrict__ b_out,      // [1]
    float*       __restrict__ out)        // [B]
{
    __shared__ int   s_off[2 * FPP];                   // byte offsets into g_comb
    __shared__ unsigned long long s_valp[FPP];         // v packed as f32x2
    __shared__ float s_red[GTH_THREADS / 32];

    const int b   = blockIdx.x;
    const int tid = threadIdx.x;

    if (tid < FPP) {
        s_off[tid]       = stm_feat[b * FPP + tid] << 11;   // *2048 B/row
        s_off[FPP + tid] = nstm_feat[b * FPP + tid] << 11;
        const float v    = values[b * FPP + tid];
        s_valp[tid]      = pack_f2(v, v);
    }
    __syncthreads();

    const int d = tid * 8;                 // 8 dims per thread
    const char* base = (const char*)g_comb + tid * 16;

    float p = side_accum(base, s_off,       s_valp, b_ft, b_fft, W_out,          d)
            + side_accum(base, s_off + FPP, s_valp, b_ft, b_fft, W_out + FT_OUT, d);

    // warp reduce (4 warps)
    #pragma unroll
    for (int off = 16; off > 0; off >>= 1)
        p += __shfl_down_sync(0xffffffffu, p, off);
    if ((tid & 31) == 0) s_red[tid >> 5] = p;
    __syncthreads();

    if (tid < (GTH_THREADS / 32)) {
        float q = s_red[tid];
        #pragma unroll
        for (int off = (GTH_THREADS / 64); off > 0; off >>= 1)
            q += __shfl_down_sync(0xfu, q, off);
        if (tid == 0) {
            float x = q + b_out[0];
            out[b] = 1.0f / (1.0f + expf(-x));
        }
    }
}

extern "C" void kernel_launch(void* const* d_in, const int* in_sizes, int n_in,
                              void* d_out, int out_size) {
    // metadata order:
    // 0 values, 1 stm_feat, 2 nstm_feat, 3 batch_idx, 4 W_ft, 5 b_ft,
    // 6 W_fft, 7 b_fft, 8 W_out, 9 b_out, 10 size
    const float* values    = (const float*)d_in[0];
    const int*   stm_feat  = (const int*)d_in[1];
    const int*   nstm_feat = (const int*)d_in[2];
    const float* W_ft      = (const float*)d_in[4];
    const float* b_ft      = (const float*)d_in[5];
    const float* W_fft     = (const float*)d_in[6];
    const float* b_fft     = (const float*)d_in[7];
    const float* W_out     = (const float*)d_in[8];
    const float* b_out     = (const float*)d_in[9];
    float* out = (float*)d_out;

    const int B = out_size;  // 8192

    build_comb_kernel<<<NFEAT, BLD_THREADS>>>(W_ft, W_fft);
    nnue_gather_kernel<<<B, GTH_THREADS>>>(values, stm_feat, nstm_feat,
                                           b_ft, b_fft, W_out, b_out, out);
}

// round 9
// speedup vs baseline: 1.0830x; 1.0830x over previous
#include <cuda_runtime.h>
#include <cuda_bf16.h>
#include <math.h>

// NNUE HalfKA inference, two-phase:
//  Phase 1: g_comb[f] = bf16(W_ft[f] + W_fft[f % 768])   (96 MB, mostly L2-resident)
//  Phase 2: per batch element, gather 2x32 bf16 rows from g_comb,
//           fp32 (packed f32x2 FFMA2) accumulate, biases, clip, output dot, sigmoid.
//  R5-winning loop shape: stm+nstm interleaved (2 independent 16B loads/iter).
//  This round: launch_bounds(128,12) for occupancy + __ldcg (L1 bypass) on gathers.
//
// Shapes: B=8192, FPP=32, FT_OUT=1024, N_FEAT=49152, N_VFEAT=768.

#define FT_OUT   1024
#define FPP      32
#define NVFEAT   768
#define NFEAT    49152
#define BLD_THREADS 256
#define GTH_THREADS 128   // 128 threads * 8 dims (16 B bf16) = one 2048 B row

// 96 MB combined bf16 table (static device scratch — no runtime allocation)
__device__ __nv_bfloat16 g_comb[(size_t)NFEAT * FT_OUT];

// ---- packed f32x2 helpers (sm_103a FFMA2 path; ptxas won't emit from C++) ----
__device__ __forceinline__ unsigned long long pack_f2(float a, float b) {
    unsigned long long r;
    asm("mov.b64 %0, {%1, %2};" : "=l"(r) : "f"(a), "f"(b));
    return r;
}
__device__ __forceinline__ void unpack_f2(unsigned long long r, float& a, float& b) {
    asm("mov.b64 {%0, %1}, %2;" : "=f"(a), "=f"(b) : "l"(r));
}
__device__ __forceinline__ unsigned long long fma_f2(unsigned long long a,
                                                     unsigned long long b,
                                                     unsigned long long c) {
    unsigned long long d;
    asm("fma.rn.f32x2 %0, %1, %2, %3;" : "=l"(d) : "l"(a), "l"(b), "l"(c));
    return d;
}
// bf16x2 (one u32) -> packed f32x2 (lo = bits<<16, hi = bits&0xffff0000)
__device__ __forceinline__ unsigned long long bf2_to_f2(unsigned int p) {
    unsigned long long r;
    asm("{\n\t"
        ".reg .b32 lo, hi;\n\t"
        "shl.b32 lo, %1, 16;\n\t"
        "and.b32 hi, %1, 0xffff0000;\n\t"
        "mov.b64 %0, {lo, hi};\n\t"
        "}" : "=l"(r) : "r"(p));
    return r;
}
// 16B L1-bypassing load
__device__ __forceinline__ uint4 ldcg16(const void* p) {
    uint4 v;
    asm volatile("ld.global.cg.v4.u32 {%0,%1,%2,%3}, [%4];"
                 : "=r"(v.x), "=r"(v.y), "=r"(v.z), "=r"(v.w) : "l"(p));
    return v;
}

// ---------------- Phase 1: build combined bf16 table ----------------
__global__ __launch_bounds__(BLD_THREADS)
void build_comb_kernel(const float* __restrict__ W_ft,
                       const float* __restrict__ W_fft)
{
    const int f = blockIdx.x;            // 0..NFEAT-1
    const int c = threadIdx.x * 4;       // 0..1020
    const size_t base = (size_t)f * FT_OUT + c;
    // W_ft is streamed exactly once: evict-first so it doesn't thrash the
    // freshly written comb table out of L2.
    const float4 a = __ldcs((const float4*)(W_ft + base));
    const float4 v = __ldg((const float4*)(W_fft + (size_t)(f % NVFEAT) * FT_OUT + c));

    __nv_bfloat162 lo = __floats2bfloat162_rn(a.x + v.x, a.y + v.y);
    __nv_bfloat162 hi = __floats2bfloat162_rn(a.z + v.z, a.w + v.w);
    uint2 pack;
    pack.x = *(unsigned int*)&lo;
    pack.y = *(unsigned int*)&hi;
    *(uint2*)(g_comb + base) = pack;
}

// ---------------- Phase 2: gather + epilogue ----------------
__global__ __launch_bounds__(GTH_THREADS, 12)
void nnue_gather_kernel(
    const float* __restrict__ values,     // [NNZ]
    const int*   __restrict__ stm_feat,   // [NNZ]
    const int*   __restrict__ nstm_feat,  // [NNZ]
    const float* __restrict__ b_ft,       // [1024]
    const float* __restrict__ b_fft,      // [1024]
    const float* __restrict__ W_out,      // [2048]
    const float* __restrict__ b_out,      // [1]
    float*       __restrict__ out)        // [B]
{
    __shared__ int   s_off[2 * FPP];                   // byte offsets into g_comb
    __shared__ unsigned long long s_valp[FPP];         // v packed as f32x2
    __shared__ float s_red[GTH_THREADS / 32];

    const int b   = blockIdx.x;
    const int tid = threadIdx.x;

    if (tid < FPP) {
        s_off[tid]       = stm_feat[b * FPP + tid] << 11;   // *2048 B/row
        s_off[FPP + tid] = nstm_feat[b * FPP + tid] << 11;
        const float v    = values[b * FPP + tid];
        s_valp[tid]      = pack_f2(v, v);
    }
    __syncthreads();

    const int d = tid * 8;                 // 8 dims per thread
    const char* base = (const char*)g_comb + tid * 16;

    // biases -> packed f32x2 accumulators (shared init for both sides)
    unsigned long long acc_s[4], acc_n[4];
    {
        float4 bf0 = *(const float4*)(b_ft  + d);
        float4 bf1 = *(const float4*)(b_ft  + d + 4);
        float4 bb0 = *(const float4*)(b_fft + d);
        float4 bb1 = *(const float4*)(b_fft + d + 4);
        acc_s[0] = pack_f2(bf0.x + bb0.x, bf0.y + bb0.y);
        acc_s[1] = pack_f2(bf0.z + bb0.z, bf0.w + bb0.w);
        acc_s[2] = pack_f2(bf1.x + bb1.x, bf1.y + bb1.y);
        acc_s[3] = pack_f2(bf1.z + bb1.z, bf1.w + bb1.w);
        acc_n[0] = acc_s[0]; acc_n[1] = acc_s[1];
        acc_n[2] = acc_s[2]; acc_n[3] = acc_s[3];
    }

    // Interleaved: 2 independent 16B loads per iter, unroll 4
    #pragma unroll 4
    for (int i = 0; i < FPP; i++) {
        const unsigned long long vv = s_valp[i];
        const uint4 ps = ldcg16(base + s_off[i]);         // stm row slice
        const uint4 pn = ldcg16(base + s_off[FPP + i]);   // nstm row slice

        acc_s[0] = fma_f2(bf2_to_f2(ps.x), vv, acc_s[0]);
        acc_s[1] = fma_f2(bf2_to_f2(ps.y), vv, acc_s[1]);
        acc_s[2] = fma_f2(bf2_to_f2(ps.z), vv, acc_s[2]);
        acc_s[3] = fma_f2(bf2_to_f2(ps.w), vv, acc_s[3]);
        acc_n[0] = fma_f2(bf2_to_f2(pn.x), vv, acc_n[0]);
        acc_n[1] = fma_f2(bf2_to_f2(pn.y), vv, acc_n[1]);
        acc_n[2] = fma_f2(bf2_to_f2(pn.z), vv, acc_n[2]);
        acc_n[3] = fma_f2(bf2_to_f2(pn.w), vv, acc_n[3]);
    }

    // unpack, clip, partial output dot — pairwise to keep reg pressure low
    float p = 0.f;
    {
        float a0, a1;
        float4 w;

        w = *(const float4*)(W_out + d);
        unpack_f2(acc_s[0], a0, a1);
        p = fmaf(fminf(fmaxf(a0, 0.f), 1.f), w.x, p);
        p = fmaf(fminf(fmaxf(a1, 0.f), 1.f), w.y, p);
        unpack_f2(acc_s[1], a0, a1);
        p = fmaf(fminf(fmaxf(a0, 0.f), 1.f), w.z, p);
        p = fmaf(fminf(fmaxf(a1, 0.f), 1.f), w.w, p);
        w = *(const float4*)(W_out + d + 4);
        unpack_f2(acc_s[2], a0, a1);
        p = fmaf(fminf(fmaxf(a0, 0.f), 1.f), w.x, p);
        p = fmaf(fminf(fmaxf(a1, 0.f), 1.f), w.y, p);
        unpack_f2(acc_s[3], a0, a1);
        p = fmaf(fminf(fmaxf(a0, 0.f), 1.f), w.z, p);
        p = fmaf(fminf(fmaxf(a1, 0.f), 1.f), w.w, p);

        w = *(const float4*)(W_out + FT_OUT + d);
        unpack_f2(acc_n[0], a0, a1);
        p = fmaf(fminf(fmaxf(a0, 0.f), 1.f), w.x, p);
        p = fmaf(fminf(fmaxf(a1, 0.f), 1.f), w.y, p);
        unpack_f2(acc_n[1], a0, a1);
        p = fmaf(fminf(fmaxf(a0, 0.f), 1.f), w.z, p);
        p = fmaf(fminf(fmaxf(a1, 0.f), 1.f), w.w, p);
        w = *(const float4*)(W_out + FT_OUT + d + 4);
        unpack_f2(acc_n[2], a0, a1);
        p = fmaf(fminf(fmaxf(a0, 0.f), 1.f), w.x, p);
        p = fmaf(fminf(fmaxf(a1, 0.f), 1.f), w.y, p);
        unpack_f2(acc_n[3], a0, a1);
        p = fmaf(fminf(fmaxf(a0, 0.f), 1.f), w.z, p);
        p = fmaf(fminf(fmaxf(a1, 0.f), 1.f), w.w, p);
    }

    // warp reduce (4 warps)
    #pragma unroll
    for (int off = 16; off > 0; off >>= 1)
        p += __shfl_down_sync(0xffffffffu, p, off);
    if ((tid & 31) == 0) s_red[tid >> 5] = p;
    __syncthreads();

    if (tid < (GTH_THREADS / 32)) {
        float q = s_red[tid];
        #pragma unroll
        for (int off = (GTH_THREADS / 64); off > 0; off >>= 1)
            q += __shfl_down_sync(0xfu, q, off);
        if (tid == 0) {
            float x = q + b_out[0];
            out[b] = 1.0f / (1.0f + expf(-x));
        }
    }
}

extern "C" void kernel_launch(void* const* d_in, const int* in_sizes, int n_in,
                              void* d_out, int out_size) {
    // metadata order:
    // 0 values, 1 stm_feat, 2 nstm_feat, 3 batch_idx, 4 W_ft, 5 b_ft,
    // 6 W_fft, 7 b_fft, 8 W_out, 9 b_out, 10 size
    const float* values    = (const float*)d_in[0];
    const int*   stm_feat  = (const int*)d_in[1];
    const int*   nstm_feat = (const int*)d_in[2];
    const float* W_ft      = (const float*)d_in[4];
    const float* b_ft      = (const float*)d_in[5];
    const float* W_fft     = (const float*)d_in[6];
    const float* b_fft     = (const float*)d_in[7];
    const float* W_out     = (const float*)d_in[8];
    const float* b_out     = (const float*)d_in[9];
    float* out = (float*)d_out;

    const int B = out_size;  // 8192

    build_comb_kernel<<<NFEAT, BLD_THREADS>>>(W_ft, W_fft);
    nnue_gather_kernel<<<B, GTH_THREADS>>>(values, stm_feat, nstm_feat,
                                           b_ft, b_fft, W_out, b_out, out);
}